// round 11
// baseline (speedup 1.0000x reference)
#include <cuda_runtime.h>
#include <cuda_bf16.h>
#include <cstdint>

#define BQ 4
#define SQ 512
#define HQ 768
#define VQ 35000
#define JQ 45
#define NGQ 5
#define TQ 5
#define NQ (BQ*JQ)      // 180
#define H3Q (3*HQ)      // 2304
#define VPAD 35072      // 274 * 128
#define MPAD 192

// ---------------- persistent scratch (zero-initialized device globals) -----
__device__ float g_w[NQ*HQ];
__device__ float g_h[NQ*HQ];
__device__ float g_hnew[NQ*HQ];
__device__ float g_gi[NQ*H3Q];
__device__ float g_gh[NQ*H3Q];
__device__ float g_attn[NQ*SQ];
__device__ float g_ctx[NQ*HQ];
__device__ float g_pgen[NQ];
__device__ unsigned g_rowmax[NQ];
__device__ unsigned long long g_best[NQ];
__device__ float g_logits[NQ*VQ];                 // 25.2 MB

// bf16 2-way splits (padding rows stay zero forever — zero-initialized)
__device__ __nv_bfloat16 g_BH[(size_t)VPAD*HQ];
__device__ __nv_bfloat16 g_BL[(size_t)VPAD*HQ];
__device__ __nv_bfloat16 g_WihH[H3Q*HQ];
__device__ __nv_bfloat16 g_WihL[H3Q*HQ];
__device__ __nv_bfloat16 g_WhhH[H3Q*HQ];
__device__ __nv_bfloat16 g_WhhL[H3Q*HQ];
__device__ __nv_bfloat16 g_AH[MPAD*HQ];
__device__ __nv_bfloat16 g_AL[MPAD*HQ];
__device__ __nv_bfloat16 g_wH[MPAD*HQ];
__device__ __nv_bfloat16 g_wL[MPAD*HQ];
__device__ __nv_bfloat16 g_hH[MPAD*HQ];
__device__ __nv_bfloat16 g_hL[MPAD*HQ];

// monotonic float<->uint encoding (order-preserving for atomicMax)
__device__ __forceinline__ unsigned fenc(float f){
    unsigned u = __float_as_uint(f);
    return (u & 0x80000000u) ? ~u : (u | 0x80000000u);
}
__device__ __forceinline__ float fdec(unsigned e){
    return (e & 0x80000000u) ? __uint_as_float(e & 0x7FFFFFFFu) : __uint_as_float(~e);
}
__device__ __forceinline__ unsigned smem_u32(const void* p){
    unsigned a;
    asm("{ .reg .u64 t; cvta.to.shared.u64 t, %1; cvt.u32.u64 %0, t; }" : "=r"(a) : "l"(p));
    return a;
}

#define LDM_X4(r0,r1,r2,r3,addr) \
  asm volatile("ldmatrix.sync.aligned.m8n8.x4.shared.b16 {%0,%1,%2,%3}, [%4];" \
    : "=r"(r0),"=r"(r1),"=r"(r2),"=r"(r3) : "r"(addr))

#define MMA16816(d,a,b) \
  asm volatile("mma.sync.aligned.m16n8k16.row.col.f32.bf16.bf16.f32 " \
    "{%0,%1,%2,%3},{%4,%5,%6,%7},{%8,%9},{%0,%1,%2,%3};" \
    : "+f"(d[0]),"+f"(d[1]),"+f"(d[2]),"+f"(d[3]) \
    : "r"(a[0]),"r"(a[1]),"r"(a[2]),"r"(a[3]),"r"(b[0]),"r"(b[1]))

// ---------------- init: w = sum of slot-token embeddings, h = hidden[b] ----
__global__ void k_init_state(const float* __restrict__ embed,
                             const float* __restrict__ hidden,
                             const int*   __restrict__ slot){
    int n = blockIdx.x; int b = n / JQ; int j = n % JQ;
    const int* sj = slot + j*4;   // LSLOT = 4
    const float* e0 = embed + (size_t)sj[0]*HQ;
    const float* e1 = embed + (size_t)sj[1]*HQ;
    const float* e2 = embed + (size_t)sj[2]*HQ;
    const float* e3 = embed + (size_t)sj[3]*HQ;
    for (int h = threadIdx.x; h < HQ; h += blockDim.x){
        g_w[n*HQ + h] = e0[h] + e1[h] + e2[h] + e3[h];
        g_h[n*HQ + h] = hidden[b*HQ + h];
    }
}

// ---------------- fp32 -> 2x bf16 split (generic, for weights) -------------
__global__ void k_split_pair(const float* __restrict__ src,
                             __nv_bfloat16* __restrict__ dh,
                             __nv_bfloat16* __restrict__ dl, int n4){
    int i = blockIdx.x*blockDim.x + threadIdx.x;
    if (i >= n4) return;
    float4 v = ((const float4*)src)[i];
    __nv_bfloat16 h[4], l[4];
    float x;
    x = v.x; h[0] = __float2bfloat16(x); l[0] = __float2bfloat16(x - __bfloat162float(h[0]));
    x = v.y; h[1] = __float2bfloat16(x); l[1] = __float2bfloat16(x - __bfloat162float(h[1]));
    x = v.z; h[2] = __float2bfloat16(x); l[2] = __float2bfloat16(x - __bfloat162float(h[2]));
    x = v.w; h[3] = __float2bfloat16(x); l[3] = __float2bfloat16(x - __bfloat162float(h[3]));
    ((uint2*)dh)[i] = *(uint2*)h;
    ((uint2*)dl)[i] = *(uint2*)l;
}

// ---------------- per-step prep: split w & h, zero reductions --------------
__global__ void k_prep(){
    int i = blockIdx.x*blockDim.x + threadIdx.x;     // < 34560
    int y = blockIdx.y;
    if (y < 2){
        const float* src = y ? g_h : g_w;
        __nv_bfloat16* dh = y ? g_hH : g_wH;
        __nv_bfloat16* dl = y ? g_hL : g_wL;
        float4 v = ((const float4*)src)[i];
        __nv_bfloat16 h[4], l[4];
        float x;
        x = v.x; h[0]=__float2bfloat16(x); l[0]=__float2bfloat16(x-__bfloat162float(h[0]));
        x = v.y; h[1]=__float2bfloat16(x); l[1]=__float2bfloat16(x-__bfloat162float(h[1]));
        x = v.z; h[2]=__float2bfloat16(x); l[2]=__float2bfloat16(x-__bfloat162float(h[2]));
        x = v.w; h[3]=__float2bfloat16(x); l[3]=__float2bfloat16(x-__bfloat162float(h[3]));
        ((uint2*)dh)[i] = *(uint2*)h;
        ((uint2*)dl)[i] = *(uint2*)l;
    } else {
        ((float4*)g_ctx)[i] = make_float4(0.f,0.f,0.f,0.f);
        if (blockIdx.x == 0 && threadIdx.x < NQ){
            g_rowmax[threadIdx.x] = 0u;
            g_best[threadIdx.x] = 0ull;
        }
    }
}

// ======================= tensor-core split GEMM (R8 proven shape) ==========
// C[m,n] = sum_k A[m,k]*B[n,k]; A=Ah+Al, B=Bh+Bl; products hh+hl+lh.
// BM=64, BN=128, BK=32, 256 threads = 8 warps (2m x 4n), warp tile 32x32.
#define LDS 40
template<bool ROWMAX, bool BIAS>
__device__ __forceinline__
void tmm_body(const __nv_bfloat16* __restrict__ Ah, const __nv_bfloat16* __restrict__ Al,
              const __nv_bfloat16* __restrict__ Bh, const __nv_bfloat16* __restrict__ Bl,
              const float* __restrict__ bias, float* __restrict__ C,
              int bm, int bn, int M, int Nvalid, int ldc)
{
    __shared__ __align__(16) __nv_bfloat16 As[2][64*LDS];
    __shared__ __align__(16) __nv_bfloat16 Bs[2][128*LDS];
    __shared__ unsigned s_rmax[64];
    int tid = threadIdx.x, lane = tid & 31, wid = tid >> 5;
    int wm = wid >> 2, wn = wid & 3;

    float acc[2][4][4];
    #pragma unroll
    for (int mi=0;mi<2;mi++)
        #pragma unroll
        for (int ni=0;ni<4;ni++)
            #pragma unroll
            for (int f=0;f<4;f++) acc[mi][ni][f] = 0.f;

    unsigned asb[2] = { smem_u32(&As[0][0]), smem_u32(&As[1][0]) };
    unsigned bsb[2] = { smem_u32(&Bs[0][0]), smem_u32(&Bs[1][0]) };

    for (int kc = 0; kc < HQ/32; kc++){
        int k0 = kc * 32;
        // A tiles: 2 x 64 x 32 bf16 = 512 uint4
        #pragma unroll
        for (int i=0;i<2;i++){
            int idx = tid + i*256;
            int t = idx >> 8, rem = idx & 255;
            int r = rem >> 2, c = rem & 3;
            const __nv_bfloat16* src = (t ? Al : Ah) + (size_t)(bm + r)*HQ + k0 + c*8;
            *(uint4*)&As[t][r*LDS + c*8] = *(const uint4*)src;
        }
        // B tiles: 2 x 128 x 32 bf16 = 1024 uint4
        #pragma unroll
        for (int i=0;i<4;i++){
            int idx = tid + i*256;
            int t = idx >> 9, rem = idx & 511;
            int r = rem >> 2, c = rem & 3;
            const __nv_bfloat16* src = (t ? Bl : Bh) + (size_t)(bn + r)*HQ + k0 + c*8;
            *(uint4*)&Bs[t][r*LDS + c*8] = *(const uint4*)src;
        }
        __syncthreads();

        #pragma unroll
        for (int kk = 0; kk < 32; kk += 16){
            unsigned a[2][2][4];
            #pragma unroll
            for (int t=0;t<2;t++)
                #pragma unroll
                for (int mi=0;mi<2;mi++){
                    int row = wm*32 + mi*16 + (lane & 15);
                    int col = kk + ((lane >> 4) << 3);
                    unsigned ad = asb[t] + (unsigned)(row*LDS + col)*2u;
                    LDM_X4(a[t][mi][0], a[t][mi][1], a[t][mi][2], a[t][mi][3], ad);
                }
            unsigned b[2][4][2];
            #pragma unroll
            for (int t=0;t<2;t++)
                #pragma unroll
                for (int g=0;g<2;g++){
                    int row = wn*32 + g*16 + (lane & 7) + ((lane >> 4) << 3);
                    int col = kk + (((lane >> 3) & 1) << 3);
                    unsigned ad = bsb[t] + (unsigned)(row*LDS + col)*2u;
                    unsigned r0,r1,r2,r3;
                    LDM_X4(r0,r1,r2,r3, ad);
                    b[t][2*g+0][0]=r0; b[t][2*g+0][1]=r1;
                    b[t][2*g+1][0]=r2; b[t][2*g+1][1]=r3;
                }
            // products: (Ah,Bh), (Ah,Bl), (Al,Bh)
            #pragma unroll
            for (int mi=0;mi<2;mi++)
                #pragma unroll
                for (int ni=0;ni<4;ni++){
                    MMA16816(acc[mi][ni], a[0][mi], b[0][ni]);
                    MMA16816(acc[mi][ni], a[0][mi], b[1][ni]);
                    MMA16816(acc[mi][ni], a[1][mi], b[0][ni]);
                }
        }
        __syncthreads();
    }

    if (ROWMAX){
        for (int i=tid;i<64;i+=256) s_rmax[i] = 0u;
        __syncthreads();
    }
    int rloc = wm*32 + (lane >> 2);
    #pragma unroll
    for (int mi=0;mi<2;mi++){
        int r0 = rloc + mi*16;
        int gr0 = bm + r0, gr1 = gr0 + 8;
        float mx0 = -3.4e38f, mx1 = -3.4e38f;
        #pragma unroll
        for (int ni=0;ni<4;ni++){
            int c0 = bn + wn*32 + ni*8 + ((lane & 3) << 1);
            float v0=acc[mi][ni][0], v1=acc[mi][ni][1], v2=acc[mi][ni][2], v3=acc[mi][ni][3];
            if (BIAS){
                float b0v = bias[c0], b1v = bias[c0+1];
                v0 += b0v; v1 += b1v; v2 += b0v; v3 += b1v;
            }
            bool c0v = (c0 < Nvalid), c1v = (c0+1 < Nvalid);
            if (gr0 < M){
                if (c0v){ C[(size_t)gr0*ldc + c0]   = v0; mx0 = fmaxf(mx0, v0); }
                if (c1v){ C[(size_t)gr0*ldc + c0+1] = v1; mx0 = fmaxf(mx0, v1); }
            }
            if (gr1 < M){
                if (c0v){ C[(size_t)gr1*ldc + c0]   = v2; mx1 = fmaxf(mx1, v2); }
                if (c1v){ C[(size_t)gr1*ldc + c0+1] = v3; mx1 = fmaxf(mx1, v3); }
            }
        }
        if (ROWMAX){
            atomicMax(&s_rmax[r0],   fenc(mx0));
            atomicMax(&s_rmax[r0+8], fenc(mx1));
        }
    }
    if (ROWMAX){
        __syncthreads();
        if (tid < 64 && bm + tid < M)
            atomicMax(&g_rowmax[bm + tid], s_rmax[tid]);
    }
}

// vocab GEMM: grid (3, 274) — m FASTEST so the 3 CTAs sharing a B tile are
// co-resident and B streams from DRAM ~once.
__global__ __launch_bounds__(256) void k_tmm_vocab(){
    tmm_body<true,false>(g_AH, g_AL, g_BH, g_BL, nullptr, g_logits,
                         blockIdx.x*64, blockIdx.y*128, NQ, VQ, VQ);
}
// both GRU GEMMs in one launch: grid (3, 18, 2); z selects gemm
__global__ __launch_bounds__(256) void k_tmm_gru(const float* bih, const float* bhh){
    if (blockIdx.z == 0)
        tmm_body<false,true>(g_wH, g_wL, g_WihH, g_WihL, bih, g_gi,
                             blockIdx.x*64, blockIdx.y*128, NQ, H3Q, H3Q);
    else
        tmm_body<false,true>(g_hH, g_hL, g_WhhH, g_WhhL, bhh, g_gh,
                             blockIdx.x*64, blockIdx.y*128, NQ, H3Q, H3Q);
}

// ---------------- GRU combine fused with hnew split ------------------------
__global__ void k_combine_split(){
    int idx = blockIdx.x*blockDim.x + threadIdx.x;
    if (idx >= NQ*HQ) return;
    int n = idx / HQ, h = idx % HQ;
    const float* gi = g_gi + (size_t)n*H3Q;
    const float* gh = g_gh + (size_t)n*H3Q;
    float r = 1.f/(1.f + __expf(-(gi[h] + gh[h])));
    float z = 1.f/(1.f + __expf(-(gi[HQ+h] + gh[HQ+h])));
    float nn = tanhf(gi[2*HQ+h] + r*gh[2*HQ+h]);
    float hv = (1.f - z)*nn + z*g_h[idx];
    g_hnew[idx] = hv;
    __nv_bfloat16 hi = __float2bfloat16(hv);
    g_AH[idx] = hi;
    g_AL[idx] = __float2bfloat16(hv - __bfloat162float(hi));
}

// ---------------- fused attention: logits + masked softmax ----------------
__global__ __launch_bounds__(256) void k_attn(const float* __restrict__ enc,
                                              const int* __restrict__ masks){
    int n = blockIdx.x, b = n / JQ;
    int tid = threadIdx.x, lane = tid & 31, warp = tid >> 5;
    __shared__ float4 hsh[HQ/4];
    __shared__ float buf[SQ];
    __shared__ float red[256];
    for (int i = tid; i < HQ/4; i += 256)
        hsh[i] = ((const float4*)(g_hnew + (size_t)n*HQ))[i];
    __syncthreads();
    for (int s = warp; s < SQ; s += 8){
        const float4* er = (const float4*)(enc + ((size_t)b*SQ + s)*HQ);
        float acc = 0.f;
        #pragma unroll
        for (int i=0;i<6;i++){
            float4 e = er[lane + i*32];
            float4 hh = hsh[lane + i*32];
            acc += e.x*hh.x + e.y*hh.y + e.z*hh.z + e.w*hh.w;
        }
        #pragma unroll
        for (int o=16;o>0;o>>=1) acc += __shfl_down_sync(0xFFFFFFFFu, acc, o);
        if (lane == 0)
            buf[s] = (masks[b*SQ + s] != 1) ? -1e9f : acc;
    }
    __syncthreads();
    float mx = -3.4e38f;
    for (int s=tid;s<SQ;s+=256) mx = fmaxf(mx, buf[s]);
    red[tid] = mx; __syncthreads();
    for (int o=128;o>0;o>>=1){ if (tid<o) red[tid] = fmaxf(red[tid], red[tid+o]); __syncthreads(); }
    mx = red[0]; __syncthreads();
    float sm = 0.f;
    for (int s=tid;s<SQ;s+=256){ float e = __expf(buf[s]-mx); buf[s]=e; sm += e; }
    red[tid] = sm; __syncthreads();
    for (int o=128;o>0;o>>=1){ if (tid<o) red[tid] += red[tid+o]; __syncthreads(); }
    float inv = 1.f/red[0];
    for (int s=tid;s<SQ;s+=256) g_attn[n*SQ + s] = buf[s]*inv;
}

// ---------------- context -------------------------------------------------
__global__ __launch_bounds__(128) void k_context(const float* __restrict__ enc){
    int h0 = blockIdx.x*128, s0 = blockIdx.y*64, b = blockIdx.z;
    int tid = threadIdx.x;
    __shared__ float at[JQ][68];
    for (int idx = tid; idx < JQ*64; idx += 128){
        int j = idx >> 6, si = idx & 63;
        at[j][si] = g_attn[(b*JQ + j)*SQ + s0 + si];
    }
    __syncthreads();
    float acc[JQ];
    #pragma unroll
    for (int j=0;j<JQ;j++) acc[j] = 0.f;
    int h = h0 + tid;
    for (int si=0; si<64; si+=4){
        float e0 = enc[((size_t)b*SQ + s0+si+0)*HQ + h];
        float e1 = enc[((size_t)b*SQ + s0+si+1)*HQ + h];
        float e2 = enc[((size_t)b*SQ + s0+si+2)*HQ + h];
        float e3 = enc[((size_t)b*SQ + s0+si+3)*HQ + h];
        #pragma unroll
        for (int j=0;j<JQ;j++){
            float4 a4 = *(const float4*)&at[j][si];
            acc[j] = fmaf(a4.x, e0, acc[j]);
            acc[j] = fmaf(a4.y, e1, acc[j]);
            acc[j] = fmaf(a4.z, e2, acc[j]);
            acc[j] = fmaf(a4.w, e3, acc[j]);
        }
    }
    #pragma unroll
    for (int j=0;j<JQ;j++)
        atomicAdd(&g_ctx[(b*JQ + j)*HQ + h], acc[j]);
}

// ---------------- p_gen (and gate on step 0) ------------------------------
__global__ void k_pgen_gate(const float* __restrict__ wgenW, const float* __restrict__ wgenb,
                            const float* __restrict__ wgateW, const float* __restrict__ wgateb,
                            float* out_gate){
    int n = blockIdx.x; int tid = threadIdx.x;
    __shared__ float red[256];
    const float* w  = g_w    + (size_t)n*HQ;
    const float* hn = g_hnew + (size_t)n*HQ;
    const float* cx = g_ctx  + (size_t)n*HQ;
    float s = 0.f;
    for (int h=tid; h<HQ; h+=256)
        s += w[h]*wgenW[h] + hn[h]*wgenW[HQ+h] + cx[h]*wgenW[2*HQ+h];
    red[tid]=s; __syncthreads();
    for (int o=128;o>0;o>>=1){ if(tid<o) red[tid]+=red[tid+o]; __syncthreads(); }
    if (tid==0) g_pgen[n] = 1.f/(1.f + __expf(-(red[0] + wgenb[0])));
    if (out_gate){
        for (int g=0; g<NGQ; g++){
            __syncthreads();
            float sg = 0.f;
            for (int h=tid; h<HQ; h+=256) sg += cx[h]*wgateW[g*HQ+h];
            red[tid]=sg; __syncthreads();
            for (int o=128;o>0;o>>=1){ if(tid<o) red[tid]+=red[tid+o]; __syncthreads(); }
            if (tid==0) out_gate[n*NGQ + g] = red[0] + wgateb[g];
        }
    }
}

// ------- fused vocab softmax + pointer scatter + full argmax --------------
__global__ __launch_bounds__(512) void k_vsoft_scatter(float* __restrict__ out,
                                                       const int* __restrict__ ids, int t){
    int n = blockIdx.x, b = n / JQ;
    int tid = threadIdx.x;
    float mx = fdec(g_rowmax[n]);
    const float* lr = g_logits + (size_t)n*VQ;
    float* orow = out + ((size_t)n*TQ + t)*VQ;
    __shared__ float red[512];
    float s = 0.f;
    for (int v = tid; v < VQ; v += 512) s += __expf(lr[v]-mx);
    red[tid]=s; __syncthreads();
    for (int o=256;o>0;o>>=1){ if(tid<o) red[tid]+=red[tid+o]; __syncthreads(); }
    float inv = 1.f/red[0];
    float pg = g_pgen[n];
    unsigned long long best = 0ull;
    for (int v = tid; v < VQ; v += 512){
        float p = pg * __expf(lr[v]-mx) * inv;
        orow[v] = p;
        unsigned long long key = ((unsigned long long)fenc(p) << 32) | (unsigned)(0x7FFFFFFF - v);
        if (key > best) best = key;
    }
    __syncthreads();
    // pointer scatter-add (own row only)
    float f = 1.f - pg;
    for (int si = tid; si < SQ; si += 512)
        atomicAdd(&orow[ids[b*SQ + si]], f * g_attn[n*SQ + si]);
    __syncthreads();
    // re-scan pointer positions for final values
    for (int si = tid; si < SQ; si += 512){
        int v = ids[b*SQ + si];
        float p = orow[v];
        unsigned long long key = ((unsigned long long)fenc(p) << 32) | (unsigned)(0x7FFFFFFF - v);
        if (key > best) best = key;
    }
    __shared__ unsigned long long redU[512];
    redU[tid]=best; __syncthreads();
    for (int o=256;o>0;o>>=1){ if(tid<o){ if (redU[tid+o] > redU[tid]) redU[tid]=redU[tid+o]; } __syncthreads(); }
    if (tid==0) g_best[n] = redU[0];
}

// ---------------- advance: w = embed[argmax], h = h_new -------------------
__global__ void k_advance(const float* __restrict__ embed){
    int n = blockIdx.x;
    int v = 0x7FFFFFFF - (int)(unsigned)(g_best[n] & 0xFFFFFFFFull);
    const float* er = embed + (size_t)v*HQ;
    for (int h = threadIdx.x; h < HQ; h += blockDim.x){
        g_w[n*HQ + h] = er[h];
        g_h[n*HQ + h] = g_hnew[n*HQ + h];
    }
}

// ---------------- host launcher -------------------------------------------
extern "C" void kernel_launch(void* const* d_in, const int* in_sizes, int n_in,
                              void* d_out, int out_size)
{
    const int*   input_ids = (const int*)  d_in[0];
    const float* enc       = (const float*)d_in[1];
    const float* hidden    = (const float*)d_in[2];
    const int*   masks     = (const int*)  d_in[3];
    const int*   slot      = (const int*)  d_in[4];
    int off = (n_in >= 15 && in_sizes[5] == 1) ? 1 : 0;
    const float* embed  = (const float*)d_in[5+off];
    const float* Wih    = (const float*)d_in[6+off];
    const float* Whh    = (const float*)d_in[7+off];
    const float* bih    = (const float*)d_in[8+off];
    const float* bhh    = (const float*)d_in[9+off];
    const float* wgenW  = (const float*)d_in[10+off];
    const float* wgenb  = (const float*)d_in[11+off];
    const float* wgateW = (const float*)d_in[12+off];
    const float* wgateb = (const float*)d_in[13+off];
    float* out      = (float*)d_out;
    float* out_gate = out + (size_t)NQ*TQ*VQ;

    static bool inited = false;
    static __nv_bfloat16 *p_BH,*p_BL,*p_WihH,*p_WihL,*p_WhhH,*p_WhhL;
    if (!inited){
        cudaGetSymbolAddress((void**)&p_BH, g_BH);
        cudaGetSymbolAddress((void**)&p_BL, g_BL);
        cudaGetSymbolAddress((void**)&p_WihH, g_WihH);
        cudaGetSymbolAddress((void**)&p_WihL, g_WihL);
        cudaGetSymbolAddress((void**)&p_WhhH, g_WhhH);
        cudaGetSymbolAddress((void**)&p_WhhL, g_WhhL);
        inited = true;
    }

    k_init_state<<<NQ, 256>>>(embed, hidden, slot);
    k_split_pair<<<(VQ*HQ/4 + 255)/256, 256>>>(embed, p_BH, p_BL, VQ*HQ/4);
    k_split_pair<<<(H3Q*HQ/4 + 255)/256, 256>>>(Wih, p_WihH, p_WihL, H3Q*HQ/4);
    k_split_pair<<<(H3Q*HQ/4 + 255)/256, 256>>>(Whh, p_WhhH, p_WhhL, H3Q*HQ/4);

    for (int t = 0; t < TQ; t++){
        dim3 gP(NQ*HQ/4/256, 3);                  // 135 x 3
        k_prep<<<gP, 256>>>();

        dim3 gG(3, H3Q/128, 2);                   // 3 x 18 x 2
        k_tmm_gru<<<gG, 256>>>(bih, bhh);
        k_combine_split<<<(NQ*HQ+255)/256, 256>>>();

        k_attn<<<NQ, 256>>>(enc, masks);
        dim3 gC(HQ/128, SQ/64, BQ);
        k_context<<<gC, 128>>>(enc);
        k_pgen_gate<<<NQ, 256>>>(wgenW, wgenb, wgateW, wgateb, (t==0)? out_gate : (float*)nullptr);

        dim3 gV(3, VPAD/128);                     // 3 x 274, m fastest
        k_tmm_vocab<<<gV, 256>>>();

        k_vsoft_scatter<<<NQ, 512>>>(out, input_ids, t);
        k_advance<<<NQ, 256>>>(embed);
    }
    (void)in_sizes; (void)n_in; (void)out_size;
}

// round 13
// speedup vs baseline: 1.1898x; 1.1898x over previous
#include <cuda_runtime.h>
#include <cuda_bf16.h>
#include <cstdint>

#define BQ 4
#define SQ 512
#define HQ 768
#define VQ 35000
#define JQ 45
#define NGQ 5
#define TQ 5
#define NQ (BQ*JQ)      // 180
#define H3Q (3*HQ)      // 2304
#define VPAD 35072      // 274 * 128
#define MPAD 192

// ---------------- persistent scratch (zero-initialized device globals) -----
__device__ float g_w[NQ*HQ];
__device__ float g_h[NQ*HQ];
__device__ float g_hnew[NQ*HQ];
__device__ float g_gi[NQ*H3Q];
__device__ float g_gh[NQ*H3Q];
__device__ float g_attn[NQ*SQ];
__device__ float g_ctx[NQ*HQ];
__device__ float g_pgen[NQ];
__device__ unsigned g_rowmax[NQ];
__device__ unsigned long long g_best[NQ];
__device__ float g_logits[NQ*VQ];                 // 25.2 MB

// bf16 2-way splits (padding rows stay zero forever — zero-initialized)
__device__ __nv_bfloat16 g_BH[(size_t)VPAD*HQ];
__device__ __nv_bfloat16 g_BL[(size_t)VPAD*HQ];
__device__ __nv_bfloat16 g_WihH[H3Q*HQ];
__device__ __nv_bfloat16 g_WihL[H3Q*HQ];
__device__ __nv_bfloat16 g_WhhH[H3Q*HQ];
__device__ __nv_bfloat16 g_WhhL[H3Q*HQ];
__device__ __nv_bfloat16 g_AH[MPAD*HQ];   // split of current h (then hnew)
__device__ __nv_bfloat16 g_AL[MPAD*HQ];
__device__ __nv_bfloat16 g_wH[MPAD*HQ];   // split of current w
__device__ __nv_bfloat16 g_wL[MPAD*HQ];

// monotonic float<->uint encoding (order-preserving for atomicMax)
__device__ __forceinline__ unsigned fenc(float f){
    unsigned u = __float_as_uint(f);
    return (u & 0x80000000u) ? ~u : (u | 0x80000000u);
}
__device__ __forceinline__ float fdec(unsigned e){
    return (e & 0x80000000u) ? __uint_as_float(e & 0x7FFFFFFFu) : __uint_as_float(~e);
}
__device__ __forceinline__ unsigned smem_u32(const void* p){
    unsigned a;
    asm("{ .reg .u64 t; cvta.to.shared.u64 t, %1; cvt.u32.u64 %0, t; }" : "=r"(a) : "l"(p));
    return a;
}

#define LDM_X4(r0,r1,r2,r3,addr) \
  asm volatile("ldmatrix.sync.aligned.m8n8.x4.shared.b16 {%0,%1,%2,%3}, [%4];" \
    : "=r"(r0),"=r"(r1),"=r"(r2),"=r"(r3) : "r"(addr))

#define MMA16816(d,a,b) \
  asm volatile("mma.sync.aligned.m16n8k16.row.col.f32.bf16.bf16.f32 " \
    "{%0,%1,%2,%3},{%4,%5,%6,%7},{%8,%9},{%0,%1,%2,%3};" \
    : "+f"(d[0]),"+f"(d[1]),"+f"(d[2]),"+f"(d[3]) \
    : "r"(a[0]),"r"(a[1]),"r"(a[2]),"r"(a[3]),"r"(b[0]),"r"(b[1]))

// ---------------- init: w/h state + their bf16 splits ---------------------
__global__ void k_init_state(const float* __restrict__ embed,
                             const float* __restrict__ hidden,
                             const int*   __restrict__ slot){
    int n = blockIdx.x; int b = n / JQ; int j = n % JQ;
    const int* sj = slot + j*4;   // LSLOT = 4
    const float* e0 = embed + (size_t)sj[0]*HQ;
    const float* e1 = embed + (size_t)sj[1]*HQ;
    const float* e2 = embed + (size_t)sj[2]*HQ;
    const float* e3 = embed + (size_t)sj[3]*HQ;
    for (int h = threadIdx.x; h < HQ; h += blockDim.x){
        float wv = e0[h] + e1[h] + e2[h] + e3[h];
        float hv = hidden[b*HQ + h];
        g_w[n*HQ + h] = wv;
        g_h[n*HQ + h] = hv;
        __nv_bfloat16 whi = __float2bfloat16(wv);
        g_wH[n*HQ + h] = whi;
        g_wL[n*HQ + h] = __float2bfloat16(wv - __bfloat162float(whi));
        __nv_bfloat16 hhi = __float2bfloat16(hv);
        g_AH[n*HQ + h] = hhi;
        g_AL[n*HQ + h] = __float2bfloat16(hv - __bfloat162float(hhi));
    }
}

// ---------------- fp32 -> 2x bf16 split (weights, once per call) ----------
__global__ void k_split_pair(const float* __restrict__ src,
                             __nv_bfloat16* __restrict__ dh,
                             __nv_bfloat16* __restrict__ dl, int n4){
    int i = blockIdx.x*blockDim.x + threadIdx.x;
    if (i >= n4) return;
    float4 v = ((const float4*)src)[i];
    __nv_bfloat16 h[4], l[4];
    float x;
    x = v.x; h[0] = __float2bfloat16(x); l[0] = __float2bfloat16(x - __bfloat162float(h[0]));
    x = v.y; h[1] = __float2bfloat16(x); l[1] = __float2bfloat16(x - __bfloat162float(h[1]));
    x = v.z; h[2] = __float2bfloat16(x); l[2] = __float2bfloat16(x - __bfloat162float(h[2]));
    x = v.w; h[3] = __float2bfloat16(x); l[3] = __float2bfloat16(x - __bfloat162float(h[3]));
    ((uint2*)dh)[i] = *(uint2*)h;
    ((uint2*)dl)[i] = *(uint2*)l;
}

// ======================= tensor-core split GEMM (R8 proven shape) ==========
// C[m,n] = sum_k A[m,k]*B[n,k]; A=Ah+Al, B=Bh+Bl; products hh+hl+lh.
// BM=64, BN=128, BK=32, 256 threads = 8 warps (2m x 4n), warp tile 32x32.
#define LDS 40
template<bool ROWMAX, bool BIAS>
__device__ __forceinline__
void tmm_body(const __nv_bfloat16* __restrict__ Ah, const __nv_bfloat16* __restrict__ Al,
              const __nv_bfloat16* __restrict__ Bh, const __nv_bfloat16* __restrict__ Bl,
              const float* __restrict__ bias, float* __restrict__ C,
              int bm, int bn, int M, int Nvalid, int ldc)
{
    __shared__ __align__(16) __nv_bfloat16 As[2][64*LDS];
    __shared__ __align__(16) __nv_bfloat16 Bs[2][128*LDS];
    __shared__ unsigned s_rmax[64];
    int tid = threadIdx.x, lane = tid & 31, wid = tid >> 5;
    int wm = wid >> 2, wn = wid & 3;

    float acc[2][4][4];
    #pragma unroll
    for (int mi=0;mi<2;mi++)
        #pragma unroll
        for (int ni=0;ni<4;ni++)
            #pragma unroll
            for (int f=0;f<4;f++) acc[mi][ni][f] = 0.f;

    unsigned asb[2] = { smem_u32(&As[0][0]), smem_u32(&As[1][0]) };
    unsigned bsb[2] = { smem_u32(&Bs[0][0]), smem_u32(&Bs[1][0]) };

    for (int kc = 0; kc < HQ/32; kc++){
        int k0 = kc * 32;
        // A tiles: 2 x 64 x 32 bf16 = 512 uint4
        #pragma unroll
        for (int i=0;i<2;i++){
            int idx = tid + i*256;
            int t = idx >> 8, rem = idx & 255;
            int r = rem >> 2, c = rem & 3;
            const __nv_bfloat16* src = (t ? Al : Ah) + (size_t)(bm + r)*HQ + k0 + c*8;
            *(uint4*)&As[t][r*LDS + c*8] = *(const uint4*)src;
        }
        // B tiles: 2 x 128 x 32 bf16 = 1024 uint4
        #pragma unroll
        for (int i=0;i<4;i++){
            int idx = tid + i*256;
            int t = idx >> 9, rem = idx & 511;
            int r = rem >> 2, c = rem & 3;
            const __nv_bfloat16* src = (t ? Bl : Bh) + (size_t)(bn + r)*HQ + k0 + c*8;
            *(uint4*)&Bs[t][r*LDS + c*8] = *(const uint4*)src;
        }
        __syncthreads();

        #pragma unroll
        for (int kk = 0; kk < 32; kk += 16){
            unsigned a[2][2][4];
            #pragma unroll
            for (int t=0;t<2;t++)
                #pragma unroll
                for (int mi=0;mi<2;mi++){
                    int row = wm*32 + mi*16 + (lane & 15);
                    int col = kk + ((lane >> 4) << 3);
                    unsigned ad = asb[t] + (unsigned)(row*LDS + col)*2u;
                    LDM_X4(a[t][mi][0], a[t][mi][1], a[t][mi][2], a[t][mi][3], ad);
                }
            unsigned b[2][4][2];
            #pragma unroll
            for (int t=0;t<2;t++)
                #pragma unroll
                for (int g=0;g<2;g++){
                    int row = wn*32 + g*16 + (lane & 7) + ((lane >> 4) << 3);
                    int col = kk + (((lane >> 3) & 1) << 3);
                    unsigned ad = bsb[t] + (unsigned)(row*LDS + col)*2u;
                    unsigned r0,r1,r2,r3;
                    LDM_X4(r0,r1,r2,r3, ad);
                    b[t][2*g+0][0]=r0; b[t][2*g+0][1]=r1;
                    b[t][2*g+1][0]=r2; b[t][2*g+1][1]=r3;
                }
            // products: (Ah,Bh), (Ah,Bl), (Al,Bh)
            #pragma unroll
            for (int mi=0;mi<2;mi++)
                #pragma unroll
                for (int ni=0;ni<4;ni++){
                    MMA16816(acc[mi][ni], a[0][mi], b[0][ni]);
                    MMA16816(acc[mi][ni], a[0][mi], b[1][ni]);
                    MMA16816(acc[mi][ni], a[1][mi], b[0][ni]);
                }
        }
        __syncthreads();
    }

    if (ROWMAX){
        for (int i=tid;i<64;i+=256) s_rmax[i] = 0u;
        __syncthreads();
    }
    int rloc = wm*32 + (lane >> 2);
    #pragma unroll
    for (int mi=0;mi<2;mi++){
        int r0 = rloc + mi*16;
        int gr0 = bm + r0, gr1 = gr0 + 8;
        float mx0 = -3.4e38f, mx1 = -3.4e38f;
        #pragma unroll
        for (int ni=0;ni<4;ni++){
            int c0 = bn + wn*32 + ni*8 + ((lane & 3) << 1);
            float v0=acc[mi][ni][0], v1=acc[mi][ni][1], v2=acc[mi][ni][2], v3=acc[mi][ni][3];
            if (BIAS){
                float b0v = bias[c0], b1v = bias[c0+1];
                v0 += b0v; v1 += b1v; v2 += b0v; v3 += b1v;
            }
            bool c0v = (c0 < Nvalid), c1v = (c0+1 < Nvalid);
            if (gr0 < M){
                if (c0v){ C[(size_t)gr0*ldc + c0]   = v0; mx0 = fmaxf(mx0, v0); }
                if (c1v){ C[(size_t)gr0*ldc + c0+1] = v1; mx0 = fmaxf(mx0, v1); }
            }
            if (gr1 < M){
                if (c0v){ C[(size_t)gr1*ldc + c0]   = v2; mx1 = fmaxf(mx1, v2); }
                if (c1v){ C[(size_t)gr1*ldc + c0+1] = v3; mx1 = fmaxf(mx1, v3); }
            }
        }
        if (ROWMAX){
            atomicMax(&s_rmax[r0],   fenc(mx0));
            atomicMax(&s_rmax[r0+8], fenc(mx1));
        }
    }
    if (ROWMAX){
        __syncthreads();
        if (tid < 64 && bm + tid < M)
            atomicMax(&g_rowmax[bm + tid], s_rmax[tid]);
    }
}

// vocab GEMM: grid (3, 274) — m FASTEST so the 3 CTAs sharing a B tile are
// co-resident and B streams from DRAM ~once.
__global__ __launch_bounds__(256) void k_tmm_vocab(){
    tmm_body<true,false>(g_AH, g_AL, g_BH, g_BL, nullptr, g_logits,
                         blockIdx.x*64, blockIdx.y*128, NQ, VQ, VQ);
}
// both GRU GEMMs in one launch: grid (3, 18, 2); z selects gemm.
// h operand = g_AH/g_AL (split of current h, maintained by combine/init).
__global__ __launch_bounds__(256) void k_tmm_gru(const float* bih, const float* bhh){
    if (blockIdx.z == 0)
        tmm_body<false,true>(g_wH, g_wL, g_WihH, g_WihL, bih, g_gi,
                             blockIdx.x*64, blockIdx.y*128, NQ, H3Q, H3Q);
    else
        tmm_body<false,true>(g_AH, g_AL, g_WhhH, g_WhhL, bhh, g_gh,
                             blockIdx.x*64, blockIdx.y*128, NQ, H3Q, H3Q);
}

// ---------------- GRU combine fused with hnew split ------------------------
// overwrites g_AH/g_AL with split(hnew) — consumed by vocab GEMM this step
// and as the h-split by next step's GRU.
__global__ void k_combine_split(){
    int idx = blockIdx.x*blockDim.x + threadIdx.x;
    if (idx >= NQ*HQ) return;
    int n = idx / HQ, h = idx % HQ;
    const float* gi = g_gi + (size_t)n*H3Q;
    const float* gh = g_gh + (size_t)n*H3Q;
    float r = 1.f/(1.f + __expf(-(gi[h] + gh[h])));
    float z = 1.f/(1.f + __expf(-(gi[HQ+h] + gh[HQ+h])));
    float nn = tanhf(gi[2*HQ+h] + r*gh[2*HQ+h]);
    float hv = (1.f - z)*nn + z*g_h[idx];
    g_hnew[idx] = hv;
    __nv_bfloat16 hi = __float2bfloat16(hv);
    g_AH[idx] = hi;
    g_AL[idx] = __float2bfloat16(hv - __bfloat162float(hi));
}

// ---------------- attention logits ----------------------------------------
__global__ void k_attn_logits(const float* __restrict__ enc){
    int s = blockIdx.x, b = blockIdx.y;
    __shared__ float es[HQ];
    for (int h = threadIdx.x; h < HQ; h += blockDim.x)
        es[h] = enc[((size_t)b*SQ + s)*HQ + h];
    __syncthreads();
    int warp = threadIdx.x >> 5, lane = threadIdx.x & 31;
    for (int j = warp; j < JQ; j += 8){
        int n = b*JQ + j;
        const float* hr = g_hnew + (size_t)n*HQ;
        float acc = 0.f;
        for (int h = lane; h < HQ; h += 32) acc = fmaf(es[h], hr[h], acc);
        #pragma unroll
        for (int o=16;o>0;o>>=1) acc += __shfl_down_sync(0xFFFFFFFFu, acc, o);
        if (lane == 0) g_attn[n*SQ + s] = acc;
    }
}

// ---------------- masked softmax over S + per-row resets -------------------
__global__ void k_attn_softmax(const int* __restrict__ masks){
    int n = blockIdx.x; int b = n / JQ;
    int tid = threadIdx.x;
    __shared__ float buf[SQ];
    __shared__ float red[256];
    // fold per-step resets: ctx row, rowmax, best (runs before their users)
    for (int h = tid; h < HQ; h += 256) g_ctx[n*HQ + h] = 0.f;
    if (tid == 0){ g_rowmax[n] = 0u; g_best[n] = 0ull; }
    float mx = -3.4e38f;
    for (int s=tid;s<SQ;s+=256){
        float v = g_attn[n*SQ + s];
        if (masks[b*SQ + s] != 1) v = -1e9f;
        buf[s] = v;
        mx = fmaxf(mx, v);
    }
    red[tid] = mx; __syncthreads();
    for (int o=128;o>0;o>>=1){ if (tid<o) red[tid] = fmaxf(red[tid], red[tid+o]); __syncthreads(); }
    mx = red[0]; __syncthreads();
    float sm = 0.f;
    for (int s=tid;s<SQ;s+=256){ float e = __expf(buf[s]-mx); buf[s]=e; sm += e; }
    red[tid] = sm; __syncthreads();
    for (int o=128;o>0;o>>=1){ if (tid<o) red[tid] += red[tid+o]; __syncthreads(); }
    float inv = 1.f/red[0];
    for (int s=tid;s<SQ;s+=256) g_attn[n*SQ + s] = buf[s]*inv;
}

// ---------------- context -------------------------------------------------
__global__ __launch_bounds__(128) void k_context(const float* __restrict__ enc){
    int h0 = blockIdx.x*128, s0 = blockIdx.y*64, b = blockIdx.z;
    int tid = threadIdx.x;
    __shared__ float at[JQ][68];
    for (int idx = tid; idx < JQ*64; idx += 128){
        int j = idx >> 6, si = idx & 63;
        at[j][si] = g_attn[(b*JQ + j)*SQ + s0 + si];
    }
    __syncthreads();
    float acc[JQ];
    #pragma unroll
    for (int j=0;j<JQ;j++) acc[j] = 0.f;
    int h = h0 + tid;
    for (int si=0; si<64; si+=4){
        float e0 = enc[((size_t)b*SQ + s0+si+0)*HQ + h];
        float e1 = enc[((size_t)b*SQ + s0+si+1)*HQ + h];
        float e2 = enc[((size_t)b*SQ + s0+si+2)*HQ + h];
        float e3 = enc[((size_t)b*SQ + s0+si+3)*HQ + h];
        #pragma unroll
        for (int j=0;j<JQ;j++){
            float4 a4 = *(const float4*)&at[j][si];
            acc[j] = fmaf(a4.x, e0, acc[j]);
            acc[j] = fmaf(a4.y, e1, acc[j]);
            acc[j] = fmaf(a4.z, e2, acc[j]);
            acc[j] = fmaf(a4.w, e3, acc[j]);
        }
    }
    #pragma unroll
    for (int j=0;j<JQ;j++)
        atomicAdd(&g_ctx[(b*JQ + j)*HQ + h], acc[j]);
}

// ---------------- p_gen (and gate on step 0) ------------------------------
__global__ void k_pgen_gate(const float* __restrict__ wgenW, const float* __restrict__ wgenb,
                            const float* __restrict__ wgateW, const float* __restrict__ wgateb,
                            float* out_gate){
    int n = blockIdx.x; int tid = threadIdx.x;
    __shared__ float red[256];
    const float* w  = g_w    + (size_t)n*HQ;
    const float* hn = g_hnew + (size_t)n*HQ;
    const float* cx = g_ctx  + (size_t)n*HQ;
    float s = 0.f;
    for (int h=tid; h<HQ; h+=256)
        s += w[h]*wgenW[h] + hn[h]*wgenW[HQ+h] + cx[h]*wgenW[2*HQ+h];
    red[tid]=s; __syncthreads();
    for (int o=128;o>0;o>>=1){ if(tid<o) red[tid]+=red[tid+o]; __syncthreads(); }
    if (tid==0) g_pgen[n] = 1.f/(1.f + __expf(-(red[0] + wgenb[0])));
    if (out_gate){
        for (int g=0; g<NGQ; g++){
            __syncthreads();
            float sg = 0.f;
            for (int h=tid; h<HQ; h+=256) sg += cx[h]*wgateW[g*HQ+h];
            red[tid]=sg; __syncthreads();
            for (int o=128;o>0;o>>=1){ if(tid<o) red[tid]+=red[tid+o]; __syncthreads(); }
            if (tid==0) out_gate[n*NGQ + g] = red[0] + wgateb[g];
        }
    }
}

// ---------------- fused vocab softmax: sum, scale+write, base argmax ------
__global__ __launch_bounds__(512) void k_vsoftmax(float* __restrict__ out, int t){
    int n = blockIdx.x;
    int tid = threadIdx.x;
    float mx = fdec(g_rowmax[n]);
    const float* lr = g_logits + (size_t)n*VQ;
    float* orow = out + ((size_t)n*TQ + t)*VQ;
    __shared__ float red[512];
    float s = 0.f;
    for (int v = tid; v < VQ; v += 512) s += __expf(lr[v]-mx);
    red[tid]=s; __syncthreads();
    for (int o=256;o>0;o>>=1){ if(tid<o) red[tid]+=red[tid+o]; __syncthreads(); }
    float inv = 1.f/red[0];
    float pg = g_pgen[n];
    unsigned long long best = 0ull;
    for (int v = tid; v < VQ; v += 512){
        float p = pg * __expf(lr[v]-mx) * inv;
        orow[v] = p;
        unsigned long long key = ((unsigned long long)fenc(p) << 32) | (unsigned)(0x7FFFFFFF - v);
        if (key > best) best = key;
    }
    __shared__ unsigned long long redU[512];
    redU[tid]=best; __syncthreads();
    for (int o=256;o>0;o>>=1){ if(tid<o){ if (redU[tid+o] > redU[tid]) redU[tid]=redU[tid+o]; } __syncthreads(); }
    if (tid==0) atomicMax(&g_best[n], redU[0]);
}

// ---------------- pointer scatter-add + pointer argmax (fused) ------------
__global__ void k_scatter_argmax(float* __restrict__ out, const int* __restrict__ ids, int t){
    int n = blockIdx.x; int b = n / JQ;
    int tid = threadIdx.x;
    float f = 1.f - g_pgen[n];
    float* orow = out + ((size_t)n*TQ + t)*VQ;
    for (int s = tid; s < SQ; s += 256)
        atomicAdd(&orow[ids[b*SQ + s]], f * g_attn[n*SQ + s]);
    __syncthreads();
    unsigned long long best = 0ull;
    for (int s = tid; s < SQ; s += 256){
        int v = ids[b*SQ + s];
        float p = orow[v];
        unsigned long long key = ((unsigned long long)fenc(p) << 32) | (unsigned)(0x7FFFFFFF - v);
        if (key > best) best = key;
    }
    __shared__ unsigned long long redU[256];
    redU[tid]=best; __syncthreads();
    for (int o=128;o>0;o>>=1){ if(tid<o){ if (redU[tid+o] > redU[tid]) redU[tid]=redU[tid+o]; } __syncthreads(); }
    if (tid==0) atomicMax(&g_best[n], redU[0]);
}

// ---------------- advance: w = embed[argmax] (+split), h = h_new ----------
__global__ void k_advance(const float* __restrict__ embed){
    int n = blockIdx.x;
    int v = 0x7FFFFFFF - (int)(unsigned)(g_best[n] & 0xFFFFFFFFull);
    const float* er = embed + (size_t)v*HQ;
    for (int h = threadIdx.x; h < HQ; h += blockDim.x){
        float wv = er[h];
        g_w[n*HQ + h] = wv;
        g_h[n*HQ + h] = g_hnew[n*HQ + h];
        __nv_bfloat16 hi = __float2bfloat16(wv);
        g_wH[n*HQ + h] = hi;
        g_wL[n*HQ + h] = __float2bfloat16(wv - __bfloat162float(hi));
    }
}

// ---------------- host launcher -------------------------------------------
extern "C" void kernel_launch(void* const* d_in, const int* in_sizes, int n_in,
                              void* d_out, int out_size)
{
    const int*   input_ids = (const int*)  d_in[0];
    const float* enc       = (const float*)d_in[1];
    const float* hidden    = (const float*)d_in[2];
    const int*   masks     = (const int*)  d_in[3];
    const int*   slot      = (const int*)  d_in[4];
    int off = (n_in >= 15 && in_sizes[5] == 1) ? 1 : 0;
    const float* embed  = (const float*)d_in[5+off];
    const float* Wih    = (const float*)d_in[6+off];
    const float* Whh    = (const float*)d_in[7+off];
    const float* bih    = (const float*)d_in[8+off];
    const float* bhh    = (const float*)d_in[9+off];
    const float* wgenW  = (const float*)d_in[10+off];
    const float* wgenb  = (const float*)d_in[11+off];
    const float* wgateW = (const float*)d_in[12+off];
    const float* wgateb = (const float*)d_in[13+off];
    float* out      = (float*)d_out;
    float* out_gate = out + (size_t)NQ*TQ*VQ;

    static bool inited = false;
    static __nv_bfloat16 *p_BH,*p_BL,*p_WihH,*p_WihL,*p_WhhH,*p_WhhL;
    if (!inited){
        cudaGetSymbolAddress((void**)&p_BH, g_BH);
        cudaGetSymbolAddress((void**)&p_BL, g_BL);
        cudaGetSymbolAddress((void**)&p_WihH, g_WihH);
        cudaGetSymbolAddress((void**)&p_WihL, g_WihL);
        cudaGetSymbolAddress((void**)&p_WhhH, g_WhhH);
        cudaGetSymbolAddress((void**)&p_WhhL, g_WhhL);
        inited = true;
    }

    k_init_state<<<NQ, 256>>>(embed, hidden, slot);
    k_split_pair<<<(VQ*HQ/4 + 255)/256, 256>>>(embed, p_BH, p_BL, VQ*HQ/4);
    k_split_pair<<<(H3Q*HQ/4 + 255)/256, 256>>>(Wih, p_WihH, p_WihL, H3Q*HQ/4);
    k_split_pair<<<(H3Q*HQ/4 + 255)/256, 256>>>(Whh, p_WhhH, p_WhhL, H3Q*HQ/4);

    for (int t = 0; t < TQ; t++){
        dim3 gG(3, H3Q/128, 2);                   // 3 x 18 x 2
        k_tmm_gru<<<gG, 256>>>(bih, bhh);
        k_combine_split<<<(NQ*HQ+255)/256, 256>>>();

        dim3 gA(SQ, BQ);
        k_attn_logits<<<gA, 256>>>(enc);
        k_attn_softmax<<<NQ, 256>>>(masks);
        dim3 gC(HQ/128, SQ/64, BQ);
        k_context<<<gC, 128>>>(enc);
        k_pgen_gate<<<NQ, 256>>>(wgenW, wgenb, wgateW, wgateb, (t==0)? out_gate : (float*)nullptr);

        dim3 gV(3, VPAD/128);                     // 3 x 274, m fastest
        k_tmm_vocab<<<gV, 256>>>();

        k_vsoftmax<<<NQ, 512>>>(out, t);
        k_scatter_argmax<<<NQ, 256>>>(out, input_ids, t);
        k_advance<<<NQ, 256>>>(embed);
    }
    (void)in_sizes; (void)n_in; (void)out_size;
}